// round 16
// baseline (speedup 1.0000x reference)
#include <cuda_runtime.h>
#include <cstdint>

#define Bb 4
#define Qq 512
#define Kk 1024
#define VDd 256
#define Hh 128

#define AT2 68          // av attn smem stride (floats; 68*4=272B, 16B aligned)
#define NSLAB 4
#define SLABK 256

// Scratch (no allocations allowed).
__device__ __align__(16) float g_qp[Bb * Qq * Hh];             // 1 MB
__device__ __align__(16) float g_kp[Bb * Kk * Hh];             // 2 MB
__device__ __align__(16) float g_sc[Bb * Qq * Kk];             // 8 MB
__device__ __align__(16) float g_pt[NSLAB][Bb * Qq * VDd];     // 8 MB partials

__device__ __forceinline__ float tanh_fast(float x) {
    float y;
    asm("tanh.approx.f32 %0, %1;" : "=f"(y) : "f"(x));
    return y;
}

// Packed fp32x2 FMA: d.lo += a.lo*b.lo; d.hi += a.hi*b.hi (one instruction).
#define FMA2(d, a, b) \
    asm("fma.rn.f32x2 %0, %1, %2, %0;" : "+l"(d) : "l"(a), "l"(b))
#define PK2(d, lo, hi) \
    asm("mov.b64 %0, {%1, %2};" : "=l"(d) : "f"(lo), "f"(hi))
#define UPK2(lo, hi, v) \
    asm("mov.b64 {%0, %1}, %2;" : "=f"(lo), "=f"(hi) : "l"(v))

// ---------------------------------------------------------------------------
// Combined projection: g_qp = queries@W_q, g_kp = keys@W_k. 384 blocks.
// Inner loop packs the d-reduction into fma.rn.f32x2: operand pairs are
// adjacent components of float4 smem loads (no packing MOVs). Accumulators
// hold (even-d, odd-d) partials, horizontally added in the epilogue.
// ---------------------------------------------------------------------------
__global__ void __launch_bounds__(256)
proj_kernel(const float* __restrict__ queries,
            const float* __restrict__ W_q,
            const float* __restrict__ keys,
            const float* __restrict__ W_k) {
    __shared__ __align__(16) float a_s[16][260];   // 260*4=1040B rows (16B mult)
    __shared__ __align__(16) float w_t[128][36];   // 36*4=144B rows (16B mult)

    const int bx = blockIdx.x;
    const float* A; const float* W; float* C; int row0;
    if (bx < (Bb * Qq) / 16) { A = queries; W = W_q; C = g_qp; row0 = bx * 16; }
    else { A = keys; W = W_k; C = g_kp; row0 = (bx - (Bb * Qq) / 16) * 16; }

    const int tid = threadIdx.x;

    const float4* A4 = (const float4*)(A + (size_t)row0 * 256);
    #pragma unroll
    for (int i = 0; i < 4; i++) {
        int e = i * 256 + tid;
        ((float4*)&a_s[e >> 6][0])[e & 63] = A4[e];
    }

    const int col = tid & 127;
    const int rg  = tid >> 7;
    unsigned long long acc2[8];
    #pragma unroll
    for (int i = 0; i < 8; i++) acc2[i] = 0ull;

    for (int dc = 0; dc < 256; dc += 32) {
        __syncthreads();
        // W chunk 32x128 -> transposed w_t[c][r].
        #pragma unroll
        for (int i = 0; i < 16; i++) {
            int idx = i * 256 + tid;
            int r = idx >> 7, c = idx & 127;
            w_t[c][r] = W[(size_t)(dc + r) * 128 + c];
        }
        __syncthreads();
        const ulonglong2* wp2 = (const ulonglong2*)&w_t[col][0];
        #pragma unroll
        for (int d4 = 0; d4 < 8; d4++) {
            ulonglong2 wp = wp2[d4];   // (w_d,w_d+1), (w_d+2,w_d+3)
            #pragma unroll
            for (int i = 0; i < 8; i++) {
                ulonglong2 ap = ((const ulonglong2*)&a_s[rg * 8 + i][dc])[d4];
                FMA2(acc2[i], ap.x, wp.x);
                FMA2(acc2[i], ap.y, wp.y);
            }
        }
    }
    __syncthreads();
    #pragma unroll
    for (int i = 0; i < 8; i++) {
        float lo, hi;
        UPK2(lo, hi, acc2[i]);
        C[(size_t)(row0 + rg * 8 + i) * 128 + col] = lo + hi;
    }
}

// ---------------------------------------------------------------------------
// Scores: 64q x 64k tile, 4x4 micro-tile, fp32 tanh (MUFU wall; best known
// form). Smem tiles transposed [h][row]. Masked tiles exit immediately.
// ---------------------------------------------------------------------------
__global__ void __launch_bounds__(256)
scores_kernel(const float* __restrict__ w_v,
              const int* __restrict__ valid_lens) {
    const int b  = blockIdx.z;
    const int k0 = blockIdx.x * 64;
    if (k0 >= valid_lens[b]) return;
    const int q0 = blockIdx.y * 64;

    extern __shared__ float sm[];
    float* qt = sm;                  // [h][qrow] 32 KB
    float* kt = qt + 128 * 64;       // [h][krow] 32 KB
    float* ws = kt + 128 * 64;       // 128

    const int tid = threadIdx.x;
    if (tid < 128) ws[tid] = w_v[tid];

    const float4* qp4 = (const float4*)(g_qp + (size_t)(b * Qq + q0) * Hh);
    const float4* kp4 = (const float4*)(g_kp + (size_t)(b * Kk + k0) * Hh);

    #pragma unroll
    for (int i = 0; i < 8; i++) {
        int t   = i * 256 + tid;
        int row = t & 63, c4 = t >> 6;
        float4 qv = qp4[row * 32 + c4];
        float4 kv = kp4[row * 32 + c4];
        int h = 4 * c4;
        qt[(h + 0) * 64 + row] = qv.x;
        qt[(h + 1) * 64 + row] = qv.y;
        qt[(h + 2) * 64 + row] = qv.z;
        qt[(h + 3) * 64 + row] = qv.w;
        kt[(h + 0) * 64 + row] = kv.x;
        kt[(h + 1) * 64 + row] = kv.y;
        kt[(h + 2) * 64 + row] = kv.z;
        kt[(h + 3) * 64 + row] = kv.w;
    }
    __syncthreads();

    const int tx = tid & 15;
    const int ty = tid >> 4;

    float acc[4][4];
    #pragma unroll
    for (int i = 0; i < 4; i++)
        #pragma unroll
        for (int j = 0; j < 4; j++) acc[i][j] = 0.f;

    #pragma unroll 4
    for (int h = 0; h < 128; h++) {
        float w = ws[h];
        float4 qv = *(const float4*)&qt[h * 64 + 4 * ty];
        float4 kv = *(const float4*)&kt[h * 64 + 4 * tx];
        float qa[4] = {qv.x, qv.y, qv.z, qv.w};
        float ka[4] = {kv.x, kv.y, kv.z, kv.w};
        #pragma unroll
        for (int i = 0; i < 4; i++)
            #pragma unroll
            for (int j = 0; j < 4; j++)
                acc[i][j] = fmaf(w, tanh_fast(qa[i] + ka[j]), acc[i][j]);
    }

    #pragma unroll
    for (int i = 0; i < 4; i++) {
        float4 r = make_float4(acc[i][0], acc[i][1], acc[i][2], acc[i][3]);
        *(float4*)&g_sc[(size_t)(b * Qq + q0 + 4 * ty + i) * Kk + k0 + 4 * tx] = r;
    }
}

// ---------------------------------------------------------------------------
// Softmax over k < vl; zeros written up to roundup(vl,64) (AV reads that far).
// ---------------------------------------------------------------------------
__global__ void softmax_kernel(const int* __restrict__ valid_lens) {
    const int row = blockIdx.x;
    const int b   = row >> 9;
    const int vl  = valid_lens[b];
    const int vl64 = (vl + 63) & ~63;
    const int tid = threadIdx.x;
    const float NINF = __int_as_float(0xff800000);

    float4* p = (float4*)&g_sc[(size_t)row * Kk];
    const int k = 4 * tid;
    const bool live = (k < vl64);
    float4 v = live ? p[tid] : make_float4(NINF, NINF, NINF, NINF);
    float e0 = (k     < vl) ? v.x : NINF;
    float e1 = (k + 1 < vl) ? v.y : NINF;
    float e2 = (k + 2 < vl) ? v.z : NINF;
    float e3 = (k + 3 < vl) ? v.w : NINF;

    __shared__ float redm[8];
    __shared__ float reds[8];
    const int wid = tid >> 5, lid = tid & 31;

    float m = fmaxf(fmaxf(e0, e1), fmaxf(e2, e3));
    #pragma unroll
    for (int o = 16; o; o >>= 1) m = fmaxf(m, __shfl_xor_sync(~0u, m, o));
    if (lid == 0) redm[wid] = m;
    __syncthreads();
    m = redm[0];
    #pragma unroll
    for (int i = 1; i < 8; i++) m = fmaxf(m, redm[i]);

    float p0 = (k     < vl) ? __expf(e0 - m) : 0.f;
    float p1 = (k + 1 < vl) ? __expf(e1 - m) : 0.f;
    float p2 = (k + 2 < vl) ? __expf(e2 - m) : 0.f;
    float p3 = (k + 3 < vl) ? __expf(e3 - m) : 0.f;

    float s = p0 + p1 + p2 + p3;
    #pragma unroll
    for (int o = 16; o; o >>= 1) s += __shfl_xor_sync(~0u, s, o);
    if (lid == 0) reds[wid] = s;
    __syncthreads();
    s = reds[0];
    #pragma unroll
    for (int i = 1; i < 8; i++) s += reds[i];

    float inv = __frcp_rn(s);
    if (live) p[tid] = make_float4(p0 * inv, p1 * inv, p2 * inv, p3 * inv);
}

// ---------------------------------------------------------------------------
// AV partial: k split in NSLAB=4 slabs -> g_pt[s]. Tile 64q x 64v, 256 thr,
// 4q x 4v per thread. f32x2: k-pairs packed -- (w_k,w_k+1) comes free from
// the attn float4, V pairs built with 8 PK2 per 4k shared across 4 q-rows.
// Accumulators hold (even-k, odd-k) partials, added in the epilogue.
// ---------------------------------------------------------------------------
__global__ void __launch_bounds__(256)
av_kernel(const float* __restrict__ values,
          const int* __restrict__ valid_lens) {
    __shared__ __align__(16) float at_s[64 * AT2];
    __shared__ __align__(16) float vs_s[64 * 64];

    const int z   = blockIdx.z;
    const int b   = z >> 2;
    const int s   = z & 3;
    const int vl  = valid_lens[b];
    const int kbeg = s * SLABK;
    if (kbeg >= vl) return;
    const int kend = (vl < kbeg + SLABK) ? vl : (kbeg + SLABK);

    const int q0  = blockIdx.y * 64;
    const int v0  = blockIdx.x * 64;
    const int tid = threadIdx.x;
    const int tx  = tid & 15;
    const int ty  = tid >> 4;

    const float* attn = g_sc + (size_t)(b * Qq + q0) * Kk + kbeg;
    const float* vals = values + ((size_t)b * Kk + kbeg) * VDd + v0;

    int lr[4];
    const int lc = tid & 15;
    #pragma unroll
    for (int i = 0; i < 4; i++) lr[i] = (i * 256 + tid) >> 4;

    float4 pa[4], pv[4];
    #pragma unroll
    for (int i = 0; i < 4; i++) {
        pa[i] = ((const float4*)(attn + (size_t)lr[i] * Kk))[lc];
        pv[i] = ((const float4*)(vals + (size_t)lr[i] * VDd))[lc];
    }

    unsigned long long acc2[4][4];   // [q-row][v-comp] = (even-k, odd-k)
    #pragma unroll
    for (int i = 0; i < 4; i++)
        #pragma unroll
        for (int c = 0; c < 4; c++) acc2[i][c] = 0ull;

    const int nchunk = (kend - kbeg + 63) >> 6;
    for (int c = 0; c < nchunk; c++) {
        #pragma unroll
        for (int i = 0; i < 4; i++) {
            ((float4*)(at_s + lr[i] * AT2))[lc] = pa[i];
            ((float4*)(vs_s + lr[i] * 64))[lc] = pv[i];
        }
        __syncthreads();

        if (c + 1 < nchunk) {
            const float* an = attn + (c + 1) * 64;
            const float* vn = vals + (size_t)(c + 1) * 64 * VDd;
            #pragma unroll
            for (int i = 0; i < 4; i++) {
                pa[i] = ((const float4*)(an + (size_t)lr[i] * Kk))[lc];
                pv[i] = ((const float4*)(vn + (size_t)lr[i] * VDd))[lc];
            }
        }

        const float4* vrow = (const float4*)vs_s + tx;
        #pragma unroll 4
        for (int k4 = 0; k4 < 16; k4++) {
            // attn rows: (w_k..w_k+3) for q rows 4ty..4ty+3, as ull pairs.
            ulonglong2 aw[4];
            #pragma unroll
            for (int i = 0; i < 4; i++)
                aw[i] = ((const ulonglong2*)(at_s + (4 * ty + i) * AT2))[k4];

            float4 v0 = vrow[(4 * k4 + 0) * 16];
            float4 v1 = vrow[(4 * k4 + 1) * 16];
            float4 v2 = vrow[(4 * k4 + 2) * 16];
            float4 v3 = vrow[(4 * k4 + 3) * 16];

            unsigned long long b01x, b01y, b01z, b01w;
            unsigned long long b23x, b23y, b23z, b23w;
            PK2(b01x, v0.x, v1.x); PK2(b01y, v0.y, v1.y);
            PK2(b01z, v0.z, v1.z); PK2(b01w, v0.w, v1.w);
            PK2(b23x, v2.x, v3.x); PK2(b23y, v2.y, v3.y);
            PK2(b23z, v2.z, v3.z); PK2(b23w, v2.w, v3.w);

            #pragma unroll
            for (int i = 0; i < 4; i++) {
                FMA2(acc2[i][0], aw[i].x, b01x);
                FMA2(acc2[i][1], aw[i].x, b01y);
                FMA2(acc2[i][2], aw[i].x, b01z);
                FMA2(acc2[i][3], aw[i].x, b01w);
                FMA2(acc2[i][0], aw[i].y, b23x);
                FMA2(acc2[i][1], aw[i].y, b23y);
                FMA2(acc2[i][2], aw[i].y, b23z);
                FMA2(acc2[i][3], aw[i].y, b23w);
            }
        }
        __syncthreads();
    }

    float* pt = g_pt[s];
    #pragma unroll
    for (int i = 0; i < 4; i++) {
        float r[4];
        #pragma unroll
        for (int cc = 0; cc < 4; cc++) {
            float lo, hi;
            UPK2(lo, hi, acc2[i][cc]);
            r[cc] = lo + hi;
        }
        float4* o = (float4*)(pt + (size_t)(b * Qq + q0 + 4 * ty + i) * VDd + v0);
        o[tx] = make_float4(r[0], r[1], r[2], r[3]);
    }
}

// ---------------------------------------------------------------------------
// Reduce: out = sum over live slabs (s*SLABK < vl). 512 blocks x 256 thr.
// ---------------------------------------------------------------------------
__global__ void reduce_kernel(const int* __restrict__ valid_lens,
                              float* __restrict__ out) {
    const int e4 = blockIdx.x * 256 + threadIdx.x;
    const int b  = e4 >> 15;
    const int vl = valid_lens[b];
    float4 r = ((const float4*)g_pt[0])[e4];
    #pragma unroll
    for (int s = 1; s < NSLAB; s++) {
        if (s * SLABK < vl) {
            float4 r1 = ((const float4*)g_pt[s])[e4];
            r.x += r1.x; r.y += r1.y; r.z += r1.z; r.w += r1.w;
        }
    }
    ((float4*)out)[e4] = r;
}

// ---------------------------------------------------------------------------
extern "C" void kernel_launch(void* const* d_in, const int* in_sizes, int n_in,
                              void* d_out, int out_size) {
    const float* queries    = (const float*)d_in[0];
    const float* keys       = (const float*)d_in[1];
    const float* values     = (const float*)d_in[2];
    const int*   valid_lens = (const int*)  d_in[3];
    const float* W_q        = (const float*)d_in[4];
    const float* W_k        = (const float*)d_in[5];
    const float* w_v        = (const float*)d_in[6];
    float* out = (float*)d_out;

    proj_kernel<<<(Bb * Qq) / 16 + (Bb * Kk) / 16, 256>>>(queries, W_q, keys, W_k);

    const int sc_smem = (2 * 128 * 64 + 128) * (int)sizeof(float);
    cudaFuncSetAttribute(scores_kernel, cudaFuncAttributeMaxDynamicSharedMemorySize,
                         sc_smem);
    scores_kernel<<<dim3(Kk / 64, Qq / 64, Bb), 256, sc_smem>>>(w_v, valid_lens);

    softmax_kernel<<<Bb * Qq, 256>>>(valid_lens);

    av_kernel<<<dim3(VDd / 64, Qq / 64, NSLAB * Bb), 256>>>(values, valid_lens);

    reduce_kernel<<<(Bb * Qq * VDd) / 1024, 256>>>(valid_lens, out);
}